// round 14
// baseline (speedup 1.0000x reference)
#include <cuda_runtime.h>
#include <cuda_fp16.h>

#define B_    128
#define IN_   1024
#define OUT_  1024

constexpr float BETA    = 0.99f;
constexpr float THRESH  = 1.0f;
constexpr float RESETV  = 0.8f;
constexpr float INV_TAU = 0.05f;              // 1/20
constexpr float A_SC    = 0.005f / 128.0f;    // A / B

// ---- device scratch (static, allocation-free) ------------------------------
__device__ int   g_sIdx[B_ * 256];            // spiking-k indices per batch (ordered)
__device__ int   g_sCnt[B_];
// Ipk slot layout: within each 64-i group g, i=(g*64+r) stored at uint2 slot
// g*64 + (r&31)*2 + (r>>5)  ->  (i, i+32) adjacent uint2 = one uint4.
__device__ uint2 g_Ipk[B_ * IN_];             // (p2, q2): e^{+dp/20}, e^{-dp/20}
__device__ uint2 g_Opk[B_ * OUT_ / 2];        // per o-pair (r2, -s2)

__device__ __forceinline__ __half2 u2h(unsigned u) { return *reinterpret_cast<__half2*>(&u); }
__device__ __forceinline__ unsigned h2u(__half2 h) { return *reinterpret_cast<unsigned*>(&h); }

// ---------------------------------------------------------------------------
// Front kernel (no transpose anymore): [0,512) Ipack; [512,640) compaction.
// ---------------------------------------------------------------------------
__global__ __launch_bounds__(256) void k_front(
    const float* __restrict__ spikes,
    const float* __restrict__ dpre)
{
    if (blockIdx.x < 512) {
        int idx = blockIdx.x * 256 + threadIdx.x;  // b*IN_ + i
        float dp = (spikes[idx] > 0.0f) ? 0.0f : dpre[idx] + 1.0f;
        uint2 u;
        u.x = h2u(__float2half2_rn(__expf(dp * INV_TAU)));   // p pair
        u.y = h2u(__float2half2_rn(__expf(-dp * INV_TAU)));  // q pair
        int i = idx & (IN_ - 1);
        int b = idx >> 10;
        int g = i >> 6, r = i & 63;
        int slot = (g << 6) + ((r & 31) << 1) + (r >> 5);
        g_Ipk[b * IN_ + slot] = u;
    } else {
        // spike-index compaction for batch b (deterministic, order-preserving)
        __shared__ int wsum[8];
        __shared__ int wbase[8];
        const int b = blockIdx.x - 512;
        const int tid = threadIdx.x;
        const int lane = tid & 31, wid = tid >> 5;

        float4 sp = reinterpret_cast<const float4*>(spikes)[b * 256 + tid];
        int f0 = sp.x > 0.0f, f1 = sp.y > 0.0f, f2 = sp.z > 0.0f, f3 = sp.w > 0.0f;
        int c = f0 + f1 + f2 + f3;

        int s = c;                                 // inclusive warp scan
        #pragma unroll
        for (int d = 1; d < 32; d <<= 1) {
            int v = __shfl_up_sync(0xFFFFFFFFu, s, d);
            if (lane >= d) s += v;
        }
        if (lane == 31) wsum[wid] = s;
        __syncthreads();
        if (tid == 0) {
            int acc = 0;
            #pragma unroll
            for (int w = 0; w < 8; w++) { wbase[w] = acc; acc += wsum[w]; }
            g_sCnt[b] = acc;
        }
        __syncthreads();

        int base = wbase[wid] + (s - c);           // exclusive offset
        int k0 = tid * 4;
        int* dst = &g_sIdx[b * 256];
        if (f0) dst[base++] = k0;
        if (f1) dst[base++] = k0 + 1;
        if (f2) dst[base++] = k0 + 2;
        if (f3) dst[base  ] = k0 + 3;
    }
}

// ---------------------------------------------------------------------------
// Fused sparse matmul + LIF + Opack — smem-gather version, NO transpose.
// grid = 128 blocks, one per 8-o group. Block stages its 8 W rows (padded:
// bank = (o+k)&31 -> octet gathers spread over 8 banks), then 4 passes of
// (32 b x 8 o) threads gather-sum from smem using each batch's spike list.
// wsum accumulation order identical to previous rounds (bit-exact).
// ---------------------------------------------------------------------------
__global__ __launch_bounds__(256) void k_mm_lif(
    const float* __restrict__ W,
    const float* __restrict__ membrane, const float* __restrict__ dfire,
    float* __restrict__ out_spike, float* __restrict__ out_mem)
{
    __shared__ float sW[8][1025];                 // 32.8 KB, +1 pad -> bank spread
    const int tid = threadIdx.x;
    const int o0 = blockIdx.x * 8;

    // stage 8 W rows, float4-coalesced: 2048 float4, 8 per thread
    #pragma unroll
    for (int t = tid; t < 2048; t += 256) {
        int r = t >> 8, c4 = t & 255;
        float4 v = *reinterpret_cast<const float4*>(&W[(size_t)(o0 + r) * IN_ + c4 * 4]);
        sW[r][c4 * 4 + 0] = v.x;
        sW[r][c4 * 4 + 1] = v.y;
        sW[r][c4 * 4 + 2] = v.z;
        sW[r][c4 * 4 + 3] = v.w;
    }
    __syncthreads();

    const int ol = tid & 7;                       // o lane within group
    const int bl = tid >> 3;                      // 0..31
    const int o  = o0 + ol;

    #pragma unroll
    for (int pass = 0; pass < 4; pass++) {
        const int b = pass * 32 + bl;
        const int cnt = g_sCnt[b];
        const int* __restrict__ lst = &g_sIdx[b * 256];

        float a0 = 0.f, a1 = 0.f, a2 = 0.f, a3 = 0.f;
        int j = 0;
        for (; j + 4 <= cnt; j += 4) {
            int k0 = lst[j], k1 = lst[j + 1], k2 = lst[j + 2], k3 = lst[j + 3];
            a0 += sW[ol][k0];
            a1 += sW[ol][k1];
            a2 += sW[ol][k2];
            a3 += sW[ol][k3];
        }
        for (; j < cnt; j++)
            a0 += sW[ol][lst[j]];
        float wsum = (a0 + a1) + (a2 + a3);

        const int base = b * OUT_ + o;
        float m = membrane[base] * BETA + wsum;
        float sp = (m > THRESH) ? 1.0f : 0.0f;
        if (sp > 0.f) m -= RESETV;
        out_spike[base] = sp;
        out_mem[base]   = m;

        float df = (sp > 0.f) ? 0.0f : dfire[base] + 1.0f;
        float r  = __expf(-df * INV_TAU);
        float ns = -__expf(df * INV_TAU);
        float r1  = __shfl_xor_sync(0xFFFFFFFFu, r, 1);
        float ns1 = __shfl_xor_sync(0xFFFFFFFFu, ns, 1);
        if (!(ol & 1)) {
            uint2 u;
            u.x = h2u(__floats2half2_rn(r, r1));    // (r_o, r_o+1)
            u.y = h2u(__floats2half2_rn(ns, ns1));  // (-s_o, -s_o+1)
            g_Opk[base >> 1] = u;
        }
    }
}

// ---------------------------------------------------------------------------
// STDP via product-vs-1 test (exact at dp==df) — UNCHANGED (at its HW floor):
//   t1 = p*r < 1  <=> df > dp : contribute +t1
//   t2 = q*(-s) > -1 <=> df < dp : contribute t2
// Tile 64i x 16o, grid (64 o-blk, 16 i-blk) = 1024 blocks, 128 threads.
// 32-batch chunks; inner b-loop register-prefetched, branch-free.
// ---------------------------------------------------------------------------
__global__ __launch_bounds__(128) void k_stdp(
    const float* __restrict__ W, float* __restrict__ outW)
{
    __shared__ uint4 sI[32][32];   // 16 KB: (p,q) for i=j and i=j+32
    __shared__ uint4 sO[32][4];    //  2 KB: o-quads

    const int tid = threadIdx.x;
    const int tx = tid & 31;       // lane -> i (and i+32)
    const int wp = tid >> 5;       // warp (0..3) -> o-quad
    const int oBase = blockIdx.x * 16;
    const int iBase = blockIdx.y * 64;

    const __half2 ONE  = __float2half2_rn(1.0f);
    const __half2 NEG1 = __float2half2_rn(-1.0f);

    float accf[2][2][2];           // [i-half][o-pair][lo/hi]
    #pragma unroll
    for (int j = 0; j < 2; j++)
        #pragma unroll
        for (int c = 0; c < 2; c++) { accf[j][c][0] = 0.f; accf[j][c][1] = 0.f; }

    const uint4* Ipk4 = reinterpret_cast<const uint4*>(g_Ipk);
    const uint4* Opk4 = reinterpret_cast<const uint4*>(g_Opk);

    for (int cb = 0; cb < 4; cb++) {           // 4 chunks of 32 batches
        // sI: 32 b x 32 uint4 = 1024; 8 per thread, coalesced LDG.128
        #pragma unroll
        for (int t = tid; t < 1024; t += 128) {
            int b = t >> 5, j = t & 31;
            sI[b][j] = Ipk4[((cb * 32 + b) * IN_ + iBase) / 2 + j];
        }
        // sO: 32 b x 4 uint4 = 128; 1 per thread
        {
            int b = tid >> 2, j = tid & 3;
            sO[b][j] = Opk4[(cb * 32 + b) * (OUT_ / 4) + (oBase >> 2) + j];
        }
        __syncthreads();

        __half2 acch[2][2];
        #pragma unroll
        for (int j = 0; j < 2; j++) {
            acch[j][0] = __float2half2_rn(0.f);
            acch[j][1] = __float2half2_rn(0.f);
        }

        // software-pipelined: branch-free prefetch of (b+1)&31
        uint4 iv = sI[0][tx];
        uint4 ov = sO[0][wp];
        #pragma unroll 8
        for (int b = 0; b < 32; b++) {
            int bn = (b + 1) & 31;
            uint4 ivn = sI[bn][tx];            // LDS.128 conflict-free
            uint4 ovn = sO[bn][wp];            // LDS.128 broadcast
            __half2 pq[2][2] = {{u2h(iv.x), u2h(iv.y)}, {u2h(iv.z), u2h(iv.w)}};
            __half2 rs[2][2] = {{u2h(ov.x), u2h(ov.y)}, {u2h(ov.z), u2h(ov.w)}};
            #pragma unroll
            for (int j = 0; j < 2; j++) {      // i-half
                #pragma unroll
                for (int c = 0; c < 2; c++) {  // o-pair
                    __half2 t1 = __hmul2(pq[j][0], rs[c][0]);
                    __half2 t2 = __hmul2(pq[j][1], rs[c][1]);
                    __half2 m1 = __hlt2(t1, ONE);
                    __half2 m2 = __hgt2(t2, NEG1);
                    acch[j][c] = __hfma2(m1, t1, acch[j][c]);
                    acch[j][c] = __hfma2(m2, t2, acch[j][c]);
                }
            }
            iv = ivn; ov = ovn;
        }

        #pragma unroll
        for (int j = 0; j < 2; j++)
            #pragma unroll
            for (int c = 0; c < 2; c++) {
                accf[j][c][0] += __low2float(acch[j][c]);
                accf[j][c][1] += __high2float(acch[j][c]);
            }
        __syncthreads();
    }

    // epilogue: lanes along i -> 128B coalesced stores
    #pragma unroll
    for (int j = 0; j < 2; j++) {
        const int i = iBase + j * 32 + tx;
        #pragma unroll
        for (int c = 0; c < 2; c++) {
            #pragma unroll
            for (int h = 0; h < 2; h++) {
                int o = oBase + wp * 4 + c * 2 + h;
                size_t off = (size_t)o * IN_ + i;
                outW[off] = W[off] + accf[j][c][h] * A_SC;
            }
        }
    }
}

// ---------------------------------------------------------------------------
extern "C" void kernel_launch(void* const* d_in, const int* in_sizes, int n_in,
                              void* d_out, int out_size)
{
    const float* spikes   = (const float*)d_in[0];
    const float* W        = (const float*)d_in[1];
    const float* membrane = (const float*)d_in[2];
    const float* dpre     = (const float*)d_in[3];
    const float* dfire    = (const float*)d_in[4];

    float* out       = (float*)d_out;
    float* out_spike = out;                                   // (B, OUT)
    float* out_W     = out + B_ * OUT_;                       // (OUT, IN)
    float* out_mem   = out + B_ * OUT_ + (size_t)OUT_ * IN_;  // (B, OUT)

    k_front<<<640, 256>>>(spikes, dpre);
    k_mm_lif<<<128, 256>>>(W, membrane, dfire, out_spike, out_mem);
    k_stdp<<<dim3(64, 16), 128>>>(W, out_W);
}

// round 15
// speedup vs baseline: 1.0936x; 1.0936x over previous
#include <cuda_runtime.h>
#include <cuda_fp16.h>

#define B_    128
#define IN_   1024
#define OUT_  1024

constexpr float BETA    = 0.99f;
constexpr float THRESH  = 1.0f;
constexpr float RESETV  = 0.8f;
constexpr float INV_TAU = 0.05f;              // 1/20
constexpr float A_SC    = 0.005f / 128.0f;    // A / B

// ---- device scratch (static, allocation-free) ------------------------------
__device__ int   g_sIdx[B_ * 256];            // spiking-k indices per batch (ordered)
__device__ int   g_sCnt[B_];
// Ipk slot layout: within each 64-i group g, i=(g*64+r) stored at uint2 slot
// g*64 + (r&31)*2 + (r>>5)  ->  (i, i+32) adjacent uint2 = one uint4.
__device__ uint2 g_Ipk[B_ * IN_];             // (p2, q2): e^{+dp/20}, e^{-dp/20}
__device__ uint2 g_Opk[B_ * OUT_ / 2];        // per o-pair (r2, -s2)

__device__ __forceinline__ __half2 u2h(unsigned u) { return *reinterpret_cast<__half2*>(&u); }
__device__ __forceinline__ unsigned h2u(__half2 h) { return *reinterpret_cast<unsigned*>(&h); }

// ---------------------------------------------------------------------------
// Front kernel (no transpose): [0,512) Ipack; [512,640) compaction.
// ---------------------------------------------------------------------------
__global__ __launch_bounds__(256) void k_front(
    const float* __restrict__ spikes,
    const float* __restrict__ dpre)
{
    if (blockIdx.x < 512) {
        int idx = blockIdx.x * 256 + threadIdx.x;  // b*IN_ + i
        float dp = (spikes[idx] > 0.0f) ? 0.0f : dpre[idx] + 1.0f;
        uint2 u;
        u.x = h2u(__float2half2_rn(__expf(dp * INV_TAU)));   // p pair
        u.y = h2u(__float2half2_rn(__expf(-dp * INV_TAU)));  // q pair
        int i = idx & (IN_ - 1);
        int b = idx >> 10;
        int g = i >> 6, r = i & 63;
        int slot = (g << 6) + ((r & 31) << 1) + (r >> 5);
        g_Ipk[b * IN_ + slot] = u;
    } else {
        // spike-index compaction for batch b (deterministic, order-preserving)
        __shared__ int wsum[8];
        __shared__ int wbase[8];
        const int b = blockIdx.x - 512;
        const int tid = threadIdx.x;
        const int lane = tid & 31, wid = tid >> 5;

        float4 sp = reinterpret_cast<const float4*>(spikes)[b * 256 + tid];
        int f0 = sp.x > 0.0f, f1 = sp.y > 0.0f, f2 = sp.z > 0.0f, f3 = sp.w > 0.0f;
        int c = f0 + f1 + f2 + f3;

        int s = c;                                 // inclusive warp scan
        #pragma unroll
        for (int d = 1; d < 32; d <<= 1) {
            int v = __shfl_up_sync(0xFFFFFFFFu, s, d);
            if (lane >= d) s += v;
        }
        if (lane == 31) wsum[wid] = s;
        __syncthreads();
        if (tid == 0) {
            int acc = 0;
            #pragma unroll
            for (int w = 0; w < 8; w++) { wbase[w] = acc; acc += wsum[w]; }
            g_sCnt[b] = acc;
        }
        __syncthreads();

        int base = wbase[wid] + (s - c);           // exclusive offset
        int k0 = tid * 4;
        int* dst = &g_sIdx[b * 256];
        if (f0) dst[base++] = k0;
        if (f1) dst[base++] = k0 + 1;
        if (f2) dst[base++] = k0 + 2;
        if (f3) dst[base  ] = k0 + 3;
    }
}

// ---------------------------------------------------------------------------
// Fused sparse matmul + LIF + Opack — smem-gather with REAL parallelism.
// grid (128 o-octets, 4 b-quarters) = 512 blocks, 256 threads.
// Block stages its 8 W rows (32.8 KB; bank = (ol+k)&31 spread), then each
// thread = (o lane, 1 batch) runs the 4-way unrolled gather-sum from smem.
// wsum accumulation order identical to prior rounds.
// ---------------------------------------------------------------------------
__global__ __launch_bounds__(256) void k_mm_lif(
    const float* __restrict__ W,
    const float* __restrict__ membrane, const float* __restrict__ dfire,
    float* __restrict__ out_spike, float* __restrict__ out_mem)
{
    __shared__ float sW[8][1025];                 // 32.8 KB
    const int tid = threadIdx.x;
    const int o0 = blockIdx.x * 8;

    // stage 8 W rows, float4-coalesced: 2048 float4, 8 per thread
    #pragma unroll
    for (int t = tid; t < 2048; t += 256) {
        int r = t >> 8, c4 = t & 255;
        float4 v = *reinterpret_cast<const float4*>(&W[(size_t)(o0 + r) * IN_ + c4 * 4]);
        sW[r][c4 * 4 + 0] = v.x;
        sW[r][c4 * 4 + 1] = v.y;
        sW[r][c4 * 4 + 2] = v.z;
        sW[r][c4 * 4 + 3] = v.w;
    }
    __syncthreads();

    const int ol = tid & 7;                       // o lane within octet
    const int bl = tid >> 3;                      // 0..31
    const int b  = blockIdx.y * 32 + bl;          // this thread's batch
    const int o  = o0 + ol;

    const int cnt = g_sCnt[b];
    const int* __restrict__ lst = &g_sIdx[b * 256];

    float a0 = 0.f, a1 = 0.f, a2 = 0.f, a3 = 0.f;
    int j = 0;
    for (; j + 4 <= cnt; j += 4) {
        int k0 = lst[j], k1 = lst[j + 1], k2 = lst[j + 2], k3 = lst[j + 3];
        a0 += sW[ol][k0];
        a1 += sW[ol][k1];
        a2 += sW[ol][k2];
        a3 += sW[ol][k3];
    }
    for (; j < cnt; j++)
        a0 += sW[ol][lst[j]];
    float wsum = (a0 + a1) + (a2 + a3);

    const int base = b * OUT_ + o;
    float m = membrane[base] * BETA + wsum;
    float sp = (m > THRESH) ? 1.0f : 0.0f;
    if (sp > 0.f) m -= RESETV;
    out_spike[base] = sp;
    out_mem[base]   = m;

    float df = (sp > 0.f) ? 0.0f : dfire[base] + 1.0f;
    float r  = __expf(-df * INV_TAU);
    float ns = -__expf(df * INV_TAU);
    float r1  = __shfl_xor_sync(0xFFFFFFFFu, r, 1);
    float ns1 = __shfl_xor_sync(0xFFFFFFFFu, ns, 1);
    if (!(ol & 1)) {
        uint2 u;
        u.x = h2u(__floats2half2_rn(r, r1));    // (r_o, r_o+1)
        u.y = h2u(__floats2half2_rn(ns, ns1));  // (-s_o, -s_o+1)
        g_Opk[base >> 1] = u;
    }
}

// ---------------------------------------------------------------------------
// STDP via product-vs-1 test (exact at dp==df) — UNCHANGED (at its HW floor):
//   t1 = p*r < 1  <=> df > dp : contribute +t1
//   t2 = q*(-s) > -1 <=> df < dp : contribute t2
// Tile 64i x 16o, grid (64 o-blk, 16 i-blk) = 1024 blocks, 128 threads.
// 32-batch chunks; inner b-loop register-prefetched, branch-free.
// ---------------------------------------------------------------------------
__global__ __launch_bounds__(128) void k_stdp(
    const float* __restrict__ W, float* __restrict__ outW)
{
    __shared__ uint4 sI[32][32];   // 16 KB: (p,q) for i=j and i=j+32
    __shared__ uint4 sO[32][4];    //  2 KB: o-quads

    const int tid = threadIdx.x;
    const int tx = tid & 31;       // lane -> i (and i+32)
    const int wp = tid >> 5;       // warp (0..3) -> o-quad
    const int oBase = blockIdx.x * 16;
    const int iBase = blockIdx.y * 64;

    const __half2 ONE  = __float2half2_rn(1.0f);
    const __half2 NEG1 = __float2half2_rn(-1.0f);

    float accf[2][2][2];           // [i-half][o-pair][lo/hi]
    #pragma unroll
    for (int j = 0; j < 2; j++)
        #pragma unroll
        for (int c = 0; c < 2; c++) { accf[j][c][0] = 0.f; accf[j][c][1] = 0.f; }

    const uint4* Ipk4 = reinterpret_cast<const uint4*>(g_Ipk);
    const uint4* Opk4 = reinterpret_cast<const uint4*>(g_Opk);

    for (int cb = 0; cb < 4; cb++) {           // 4 chunks of 32 batches
        // sI: 32 b x 32 uint4 = 1024; 8 per thread, coalesced LDG.128
        #pragma unroll
        for (int t = tid; t < 1024; t += 128) {
            int b = t >> 5, j = t & 31;
            sI[b][j] = Ipk4[((cb * 32 + b) * IN_ + iBase) / 2 + j];
        }
        // sO: 32 b x 4 uint4 = 128; 1 per thread
        {
            int b = tid >> 2, j = tid & 3;
            sO[b][j] = Opk4[(cb * 32 + b) * (OUT_ / 4) + (oBase >> 2) + j];
        }
        __syncthreads();

        __half2 acch[2][2];
        #pragma unroll
        for (int j = 0; j < 2; j++) {
            acch[j][0] = __float2half2_rn(0.f);
            acch[j][1] = __float2half2_rn(0.f);
        }

        // software-pipelined: branch-free prefetch of (b+1)&31
        uint4 iv = sI[0][tx];
        uint4 ov = sO[0][wp];
        #pragma unroll 8
        for (int b = 0; b < 32; b++) {
            int bn = (b + 1) & 31;
            uint4 ivn = sI[bn][tx];            // LDS.128 conflict-free
            uint4 ovn = sO[bn][wp];            // LDS.128 broadcast
            __half2 pq[2][2] = {{u2h(iv.x), u2h(iv.y)}, {u2h(iv.z), u2h(iv.w)}};
            __half2 rs[2][2] = {{u2h(ov.x), u2h(ov.y)}, {u2h(ov.z), u2h(ov.w)}};
            #pragma unroll
            for (int j = 0; j < 2; j++) {      // i-half
                #pragma unroll
                for (int c = 0; c < 2; c++) {  // o-pair
                    __half2 t1 = __hmul2(pq[j][0], rs[c][0]);
                    __half2 t2 = __hmul2(pq[j][1], rs[c][1]);
                    __half2 m1 = __hlt2(t1, ONE);
                    __half2 m2 = __hgt2(t2, NEG1);
                    acch[j][c] = __hfma2(m1, t1, acch[j][c]);
                    acch[j][c] = __hfma2(m2, t2, acch[j][c]);
                }
            }
            iv = ivn; ov = ovn;
        }

        #pragma unroll
        for (int j = 0; j < 2; j++)
            #pragma unroll
            for (int c = 0; c < 2; c++) {
                accf[j][c][0] += __low2float(acch[j][c]);
                accf[j][c][1] += __high2float(acch[j][c]);
            }
        __syncthreads();
    }

    // epilogue: lanes along i -> 128B coalesced stores
    #pragma unroll
    for (int j = 0; j < 2; j++) {
        const int i = iBase + j * 32 + tx;
        #pragma unroll
        for (int c = 0; c < 2; c++) {
            #pragma unroll
            for (int h = 0; h < 2; h++) {
                int o = oBase + wp * 4 + c * 2 + h;
                size_t off = (size_t)o * IN_ + i;
                outW[off] = W[off] + accf[j][c][h] * A_SC;
            }
        }
    }
}

// ---------------------------------------------------------------------------
extern "C" void kernel_launch(void* const* d_in, const int* in_sizes, int n_in,
                              void* d_out, int out_size)
{
    const float* spikes   = (const float*)d_in[0];
    const float* W        = (const float*)d_in[1];
    const float* membrane = (const float*)d_in[2];
    const float* dpre     = (const float*)d_in[3];
    const float* dfire    = (const float*)d_in[4];

    float* out       = (float*)d_out;
    float* out_spike = out;                                   // (B, OUT)
    float* out_W     = out + B_ * OUT_;                       // (OUT, IN)
    float* out_mem   = out + B_ * OUT_ + (size_t)OUT_ * IN_;  // (B, OUT)

    k_front<<<640, 256>>>(spikes, dpre);
    k_mm_lif<<<dim3(128, 4), 256>>>(W, membrane, dfire, out_spike, out_mem);
    k_stdp<<<dim3(64, 16), 128>>>(W, out_W);
}

// round 16
// speedup vs baseline: 1.2808x; 1.1712x over previous
#include <cuda_runtime.h>
#include <cuda_fp16.h>

#define B_    128
#define IN_   1024
#define OUT_  1024

constexpr float BETA    = 0.99f;
constexpr float THRESH  = 1.0f;
constexpr float RESETV  = 0.8f;
constexpr float INV_TAU = 0.05f;              // 1/20
constexpr float A_SC    = 0.005f / 128.0f;    // A / B

// ---- device scratch (static, allocation-free) ------------------------------
__device__ float g_Wt[IN_ * OUT_];            // Wt[k][o] = W[o][k]
// Ipk slot layout: within each 64-i group g, i=(g*64+r) stored at uint2 slot
// g*64 + (r&31)*2 + (r>>5)  ->  (i, i+32) adjacent uint2 = one uint4.
__device__ uint2 g_Ipk[B_ * IN_];             // (p2, q2): e^{+dp/20}, e^{-dp/20}
__device__ uint2 g_Opk[B_ * OUT_ / 2];        // per o-pair (r2, -s2)

__device__ __forceinline__ __half2 u2h(unsigned u) { return *reinterpret_cast<__half2*>(&u); }
__device__ __forceinline__ unsigned h2u(__half2 h) { return *reinterpret_cast<unsigned*>(&h); }

// ---------------------------------------------------------------------------
// Front kernel: [0,1024) transpose W -> Wt (32x32 scalar tiles, R10-best);
// [1024,1536) Ipack with coalesced slot-major stores.
// ---------------------------------------------------------------------------
__global__ __launch_bounds__(256) void k_front(
    const float* __restrict__ W,
    const float* __restrict__ spikes,
    const float* __restrict__ dpre)
{
    if (blockIdx.x < 1024) {
        __shared__ float t[32][33];
        const int bx = (blockIdx.x & 31) * 32;   // k range
        const int by = (blockIdx.x >> 5) * 32;   // o range
        const int tx = threadIdx.x & 31;
        const int ty = threadIdx.x >> 5;         // 0..7
        #pragma unroll
        for (int i = 0; i < 32; i += 8)
            t[ty + i][tx] = W[(size_t)(by + ty + i) * IN_ + bx + tx];
        __syncthreads();
        #pragma unroll
        for (int i = 0; i < 32; i += 8)
            g_Wt[(size_t)(bx + ty + i) * OUT_ + by + tx] = t[tx][ty + i];
    } else {
        // Ipack: thread owns SLOT (coalesced store); source i from inverse map.
        int sidx = (blockIdx.x - 1024) * 256 + threadIdx.x;   // b*IN_ + slot
        int b  = sidx >> 10;
        int sl = sidx & (IN_ - 1);
        int sp = sl & 63;                                      // slot within group
        int i  = (sl & ~63) + (sp >> 1) + ((sp & 1) << 5);     // inverse interleave
        int src = b * IN_ + i;
        float dp = (spikes[src] > 0.0f) ? 0.0f : dpre[src] + 1.0f;
        uint2 u;
        u.x = h2u(__float2half2_rn(__expf(dp * INV_TAU)));   // p pair
        u.y = h2u(__float2half2_rn(__expf(-dp * INV_TAU)));  // q pair
        g_Ipk[sidx] = u;                                     // coalesced STG.64
    }
}

// ---------------------------------------------------------------------------
// Fused compaction + sparse matmul + LIF + Opack.
// grid (2 o-chunks of 512, 128 b). 256 threads, thread = one o-PAIR (float2).
// Block compacts its batch's spike indices into shared (order-preserving,
// identical list order as before), then gathers Wt rows from L2 (coalesced).
// ---------------------------------------------------------------------------
__global__ __launch_bounds__(256) void k_mm_lif(
    const float* __restrict__ spikes,
    const float* __restrict__ membrane, const float* __restrict__ dfire,
    float* __restrict__ out_spike, float* __restrict__ out_mem)
{
    __shared__ int sk[256];
    __shared__ int wsumS[8];
    __shared__ int wbase[8];
    __shared__ int scnt;
    const int tid = threadIdx.x;
    const int b = blockIdx.y;
    const int o0 = blockIdx.x * 512 + tid * 2;    // even o

    // ---- in-block compaction of batch b (deterministic, order-preserving)
    {
        const int lane = tid & 31, wid = tid >> 5;
        float4 sp = reinterpret_cast<const float4*>(spikes)[b * 256 + tid];
        int f0 = sp.x > 0.0f, f1 = sp.y > 0.0f, f2 = sp.z > 0.0f, f3 = sp.w > 0.0f;
        int c = f0 + f1 + f2 + f3;

        int s = c;                                 // inclusive warp scan
        #pragma unroll
        for (int d = 1; d < 32; d <<= 1) {
            int v = __shfl_up_sync(0xFFFFFFFFu, s, d);
            if (lane >= d) s += v;
        }
        if (lane == 31) wsumS[wid] = s;
        __syncthreads();
        if (tid == 0) {
            int acc = 0;
            #pragma unroll
            for (int w = 0; w < 8; w++) { wbase[w] = acc; acc += wsumS[w]; }
            scnt = acc;
        }
        __syncthreads();

        int base = wbase[wid] + (s - c);           // exclusive offset
        int k0 = tid * 4;
        if (f0) sk[base++] = k0;
        if (f1) sk[base++] = k0 + 1;
        if (f2) sk[base++] = k0 + 2;
        if (f3) sk[base  ] = k0 + 3;
        __syncthreads();
    }

    const int cnt = scnt;

    float2 a0 = make_float2(0.f, 0.f), a1 = make_float2(0.f, 0.f);
    float2 a2 = make_float2(0.f, 0.f), a3 = make_float2(0.f, 0.f);
    int j = 0;
    for (; j + 4 <= cnt; j += 4) {
        int k0 = sk[j], k1 = sk[j + 1], k2 = sk[j + 2], k3 = sk[j + 3];
        float2 w0 = *reinterpret_cast<const float2*>(&g_Wt[(size_t)k0 * OUT_ + o0]);
        float2 w1 = *reinterpret_cast<const float2*>(&g_Wt[(size_t)k1 * OUT_ + o0]);
        float2 w2 = *reinterpret_cast<const float2*>(&g_Wt[(size_t)k2 * OUT_ + o0]);
        float2 w3 = *reinterpret_cast<const float2*>(&g_Wt[(size_t)k3 * OUT_ + o0]);
        a0.x += w0.x; a0.y += w0.y;
        a1.x += w1.x; a1.y += w1.y;
        a2.x += w2.x; a2.y += w2.y;
        a3.x += w3.x; a3.y += w3.y;
    }
    for (; j < cnt; j++) {
        float2 w = *reinterpret_cast<const float2*>(&g_Wt[(size_t)sk[j] * OUT_ + o0]);
        a0.x += w.x; a0.y += w.y;
    }
    float w0 = (a0.x + a1.x) + (a2.x + a3.x);
    float w1 = (a0.y + a1.y) + (a2.y + a3.y);

    const int base = b * OUT_ + o0;
    float2 mem = *reinterpret_cast<const float2*>(&membrane[base]);
    float2 dfr = *reinterpret_cast<const float2*>(&dfire[base]);

    float m0 = mem.x * BETA + w0, m1 = mem.y * BETA + w1;
    float s0 = (m0 > THRESH) ? 1.0f : 0.0f;
    float s1 = (m1 > THRESH) ? 1.0f : 0.0f;
    if (s0 > 0.f) m0 -= RESETV;
    if (s1 > 0.f) m1 -= RESETV;

    *reinterpret_cast<float2*>(&out_spike[base]) = make_float2(s0, s1);
    *reinterpret_cast<float2*>(&out_mem[base])   = make_float2(m0, m1);

    float df0 = (s0 > 0.f) ? 0.0f : dfr.x + 1.0f;
    float df1 = (s1 > 0.f) ? 0.0f : dfr.y + 1.0f;
    uint2 u;
    u.x = h2u(__floats2half2_rn(__expf(-df0 * INV_TAU), __expf(-df1 * INV_TAU)));  // r
    u.y = h2u(__floats2half2_rn(-__expf(df0 * INV_TAU), -__expf(df1 * INV_TAU))); // -s
    g_Opk[base >> 1] = u;
}

// ---------------------------------------------------------------------------
// STDP via product-vs-1 test (exact at dp==df) — UNCHANGED (at its HW floor):
//   t1 = p*r < 1  <=> df > dp : contribute +t1
//   t2 = q*(-s) > -1 <=> df < dp : contribute t2
// Tile 64i x 16o, grid (64 o-blk, 16 i-blk) = 1024 blocks, 128 threads.
// 32-batch chunks; inner b-loop register-prefetched, branch-free.
// ---------------------------------------------------------------------------
__global__ __launch_bounds__(128) void k_stdp(
    const float* __restrict__ W, float* __restrict__ outW)
{
    __shared__ uint4 sI[32][32];   // 16 KB: (p,q) for i=j and i=j+32
    __shared__ uint4 sO[32][4];    //  2 KB: o-quads

    const int tid = threadIdx.x;
    const int tx = tid & 31;       // lane -> i (and i+32)
    const int wp = tid >> 5;       // warp (0..3) -> o-quad
    const int oBase = blockIdx.x * 16;
    const int iBase = blockIdx.y * 64;

    const __half2 ONE  = __float2half2_rn(1.0f);
    const __half2 NEG1 = __float2half2_rn(-1.0f);

    float accf[2][2][2];           // [i-half][o-pair][lo/hi]
    #pragma unroll
    for (int j = 0; j < 2; j++)
        #pragma unroll
        for (int c = 0; c < 2; c++) { accf[j][c][0] = 0.f; accf[j][c][1] = 0.f; }

    const uint4* Ipk4 = reinterpret_cast<const uint4*>(g_Ipk);
    const uint4* Opk4 = reinterpret_cast<const uint4*>(g_Opk);

    for (int cb = 0; cb < 4; cb++) {           // 4 chunks of 32 batches
        // sI: 32 b x 32 uint4 = 1024; 8 per thread, coalesced LDG.128
        #pragma unroll
        for (int t = tid; t < 1024; t += 128) {
            int b = t >> 5, j = t & 31;
            sI[b][j] = Ipk4[((cb * 32 + b) * IN_ + iBase) / 2 + j];
        }
        // sO: 32 b x 4 uint4 = 128; 1 per thread
        {
            int b = tid >> 2, j = tid & 3;
            sO[b][j] = Opk4[(cb * 32 + b) * (OUT_ / 4) + (oBase >> 2) + j];
        }
        __syncthreads();

        __half2 acch[2][2];
        #pragma unroll
        for (int j = 0; j < 2; j++) {
            acch[j][0] = __float2half2_rn(0.f);
            acch[j][1] = __float2half2_rn(0.f);
        }

        // software-pipelined: branch-free prefetch of (b+1)&31
        uint4 iv = sI[0][tx];
        uint4 ov = sO[0][wp];
        #pragma unroll 8
        for (int b = 0; b < 32; b++) {
            int bn = (b + 1) & 31;
            uint4 ivn = sI[bn][tx];            // LDS.128 conflict-free
            uint4 ovn = sO[bn][wp];            // LDS.128 broadcast
            __half2 pq[2][2] = {{u2h(iv.x), u2h(iv.y)}, {u2h(iv.z), u2h(iv.w)}};
            __half2 rs[2][2] = {{u2h(ov.x), u2h(ov.y)}, {u2h(ov.z), u2h(ov.w)}};
            #pragma unroll
            for (int j = 0; j < 2; j++) {      // i-half
                #pragma unroll
                for (int c = 0; c < 2; c++) {  // o-pair
                    __half2 t1 = __hmul2(pq[j][0], rs[c][0]);
                    __half2 t2 = __hmul2(pq[j][1], rs[c][1]);
                    __half2 m1 = __hlt2(t1, ONE);
                    __half2 m2 = __hgt2(t2, NEG1);
                    acch[j][c] = __hfma2(m1, t1, acch[j][c]);
                    acch[j][c] = __hfma2(m2, t2, acch[j][c]);
                }
            }
            iv = ivn; ov = ovn;
        }

        #pragma unroll
        for (int j = 0; j < 2; j++)
            #pragma unroll
            for (int c = 0; c < 2; c++) {
                accf[j][c][0] += __low2float(acch[j][c]);
                accf[j][c][1] += __high2float(acch[j][c]);
            }
        __syncthreads();
    }

    // epilogue: lanes along i -> 128B coalesced stores
    #pragma unroll
    for (int j = 0; j < 2; j++) {
        const int i = iBase + j * 32 + tx;
        #pragma unroll
        for (int c = 0; c < 2; c++) {
            #pragma unroll
            for (int h = 0; h < 2; h++) {
                int o = oBase + wp * 4 + c * 2 + h;
                size_t off = (size_t)o * IN_ + i;
                outW[off] = W[off] + accf[j][c][h] * A_SC;
            }
        }
    }
}

// ---------------------------------------------------------------------------
extern "C" void kernel_launch(void* const* d_in, const int* in_sizes, int n_in,
                              void* d_out, int out_size)
{
    const float* spikes   = (const float*)d_in[0];
    const float* W        = (const float*)d_in[1];
    const float* membrane = (const float*)d_in[2];
    const float* dpre     = (const float*)d_in[3];
    const float* dfire    = (const float*)d_in[4];

    float* out       = (float*)d_out;
    float* out_spike = out;                                   // (B, OUT)
    float* out_W     = out + B_ * OUT_;                       // (OUT, IN)
    float* out_mem   = out + B_ * OUT_ + (size_t)OUT_ * IN_;  // (B, OUT)

    k_front<<<1536, 256>>>(W, spikes, dpre);
    k_mm_lif<<<dim3(2, 128), 256>>>(spikes, membrane, dfire, out_spike, out_mem);
    k_stdp<<<dim3(64, 16), 128>>>(W, out_W);
}